// round 6
// baseline (speedup 1.0000x reference)
#include <cuda_runtime.h>
#include <cstdint>

#define Bn    8
#define Nn    8192
#define Cn    91
#define Mx    (Nn*(Cn-1))     // 737280 flat candidate ids per image
#define CAPc  163840          // >= max kept candidates per image
#define NB    9216            // histogram bins over score float bits >> 12
#define BASE_BIN 251084       // bits(0.05f) >> 12
#define SEL_CAP 1024
#define TPB   1024
#define TILE  256
#define DETS  100
#define CLIPV 4.135166556742356f   // log(1000/16)
#define FULLM 0xffffffffu
#define PROD_BLOCKS 256
#define ROUNDS 8                   // chunks per producer block (image-major)

// ------------------------------------------------------------------
// static device scratch (zero-initialized at load; the NMS blocks restore
// every zero they consume -> graph-replay deterministic)
// ------------------------------------------------------------------
__device__ unsigned long long g_keys[Bn][CAPc];
__device__ float4             g_box [Bn][Mx];
__device__ int                g_cnt [Bn];
__device__ int                g_hist[Bn][NB];
__device__ int                g_done[Bn];

__device__ __forceinline__ void stf(float* o, int i, float v, int n) {
    if (i < n) o[i] = v;
}

// reference-rounding IoU on offset coordinates; returns (iou > 0.5)
__device__ __forceinline__ bool iou_sup(float4 A, float4 Bx, float off) {
    float ax1 = A.x + off, ay1 = A.y + off, ax2 = A.z + off, ay2 = A.w + off;
    float bx1 = Bx.x + off, by1 = Bx.y + off, bx2 = Bx.z + off, by2 = Bx.w + off;
    float ltx = fmaxf(ax1, bx1), lty = fmaxf(ay1, by1);
    float rbx = fminf(ax2, bx2), rby = fminf(ay2, by2);
    float ww = fmaxf(rbx - ltx, 0.f), hh = fmaxf(rby - lty, 0.f);
    float inter = ww * hh;
    float a1 = (ax2 - ax1) * (ay2 - ay1);
    float a2 = (bx2 - bx1) * (by2 - by1);
    float iou = __fdiv_rn(inter, a1 + a2 - inter + 1e-9f);
    return iou > 0.5f;
}

// ------------------------------------------------------------------
// shared memory for the NMS role
// ------------------------------------------------------------------
struct SM {
    float4 sbox[SEL_CAP];               // sorted boxes        16384
    unsigned long long skey[SEL_CAP];   //                      8192
    int    slbl[SEL_CAP];               //                      4096
    int    sfx[NB];                     // suffix counts       36864
    unsigned mask[TILE * 8];            // within-tile bitmask  8192
    float4 abox[DETS];                  // accepted boxes       1600
    int    albl[DETS];                  //                       400
    unsigned supw[8];
    int    wtot[32], wexc[32];
    int    s_cnt, s_acc;
};

// ------------------------------------------------------------------
// candidate generation for one proposal (one warp)
// ------------------------------------------------------------------
__device__ __forceinline__ void cand_warp(int g, int lane,
                                          const float* __restrict__ logits,
                                          const float* __restrict__ reg,
                                          const float* __restrict__ props) {
    int b = g >> 13;
    int n = g & (Nn - 1);

    const float* L = logits + (size_t)g * Cn;
    float l0 = L[lane];
    float l1 = (lane + 32 < Cn) ? L[lane + 32] : -1e30f;
    float l2 = (lane + 64 < Cn) ? L[lane + 64] : -1e30f;

    float mx = fmaxf(l0, fmaxf(l1, l2));
    #pragma unroll
    for (int o = 16; o; o >>= 1) mx = fmaxf(mx, __shfl_xor_sync(FULLM, mx, o));

    float e0 = expf(l0 - mx);
    float e1 = (lane + 32 < Cn) ? expf(l1 - mx) : 0.0f;
    float e2 = (lane + 64 < Cn) ? expf(l2 - mx) : 0.0f;
    float s = e0 + e1 + e2;
    #pragma unroll
    for (int o = 16; o; o >>= 1) s += __shfl_xor_sync(FULLM, s, o);

    float4 p = reinterpret_cast<const float4*>(props)[g];
    float w  = p.z - p.x;
    float h  = p.w - p.y;
    float cx = p.x + 0.5f * w;
    float cy = p.y + 0.5f * h;

    const float4* Q = reinterpret_cast<const float4*>(reg + (size_t)g * (Cn * 4));

    bool  okv[3];
    float scv[3];
    float4 bxv[3];
    float pre_t = 0.0497f * s;   // conservative prefilter (>> 1ulp margin)

    #pragma unroll
    for (int k = 0; k < 3; k++) {
        int c = lane + 32 * k;
        float e = (k == 0) ? e0 : (k == 1) ? e1 : e2;
        bool ok = (c >= 1) && (c < Cn) && (e > pre_t);
        float sc = 0.f;
        float4 bx = make_float4(0.f, 0.f, 0.f, 0.f);
        if (ok) {
            sc = __fdiv_rn(e, s);          // exact softmax value
            ok = (sc > 0.05f);
            if (ok) {
                float4 q = Q[c];
                float dx = __fdiv_rn(q.x, 10.0f);
                float dy = __fdiv_rn(q.y, 10.0f);
                float dw = fminf(__fdiv_rn(q.z, 5.0f), CLIPV);
                float dh = fminf(__fdiv_rn(q.w, 5.0f), CLIPV);
                float pcx = dx * w + cx;
                float pcy = dy * h + cy;
                float pw  = expf(dw) * w;
                float ph  = expf(dh) * h;
                float x1 = fminf(fmaxf(pcx - 0.5f * pw, 0.f), 800.f);
                float y1 = fminf(fmaxf(pcy - 0.5f * ph, 0.f), 800.f);
                float x2 = fminf(fmaxf(pcx + 0.5f * pw, 0.f), 800.f);
                float y2 = fminf(fmaxf(pcy + 0.5f * ph, 0.f), 800.f);
                ok = ((x2 - x1) >= 1.0f) && ((y2 - y1) >= 1.0f);
                bx = make_float4(x1, y1, x2, y2);
            }
        }
        okv[k] = ok; scv[k] = sc; bxv[k] = bx;
    }

    unsigned mA = __ballot_sync(FULLM, okv[0]);
    unsigned mB = __ballot_sync(FULLM, okv[1]);
    unsigned mC = __ballot_sync(FULLM, okv[2]);
    int tot = __popc(mA) + __popc(mB) + __popc(mC);
    if (tot) {
        int base = 0;
        if (lane == 0) base = atomicAdd(&g_cnt[b], tot);
        base = __shfl_sync(FULLM, base, 0);
        unsigned below = (1u << lane) - 1u;
        int p0 = base + __popc(mA & below);
        int p1 = base + __popc(mA) + __popc(mB & below);
        int p2 = base + __popc(mA) + __popc(mB) + __popc(mC & below);

        #pragma unroll
        for (int k = 0; k < 3; k++) {
            if (okv[k]) {
                int pos = (k == 0) ? p0 : (k == 1) ? p1 : p2;
                if (pos < CAPc) {
                    int c = lane + 32 * k;
                    unsigned m = (unsigned)(n * 90 + (c - 1));
                    unsigned sb = __float_as_uint(scv[k]);
                    g_keys[b][pos] = ((unsigned long long)sb << 32) | (0xFFFFFFFFu - m);
                    g_box[b][m]    = bxv[k];          // box indexed by flat id
                    int bin = (int)(sb >> 12) - BASE_BIN;
                    bin = max(0, min(bin, NB - 1));
                    atomicAdd(&g_hist[b][bin], 1);
                }
            }
        }
    }
}

// ------------------------------------------------------------------
// fused kernel, single wave: 8 consumers spread at blockIdx%33==0,
// 256 persistent producers each do 8 image-major chunks.
// ------------------------------------------------------------------
__global__ __launch_bounds__(TPB) void k_fused(const float* __restrict__ logits,
                                               const float* __restrict__ reg,
                                               const float* __restrict__ props,
                                               float* __restrict__ out,
                                               int out_size) {
    extern __shared__ __align__(16) char smraw[];
    int t = threadIdx.x;
    int lane = t & 31;
    int warp = t >> 5;
    int cix = blockIdx.x / 33;

    if ((blockIdx.x % 33) != 0) {
        // ================= producer role =================
        int pb = blockIdx.x - cix - 1;            // 0..255
        #pragma unroll 1
        for (int r = 0; r < ROUNDS; r++) {
            int chunk = r * PROD_BLOCKS + pb;     // image r, chunk pb
            int g = chunk * 32 + warp;            // one proposal per warp
            cand_warp(g, lane, logits, reg, props);
            __threadfence();
            __syncthreads();
            if (t == 0) atomicAdd(&g_done[r], 1);
        }
        return;
    }

    // ================= consumer (NMS) role =================
    SM* sm = reinterpret_cast<SM*>(smraw);
    int b = cix;

    if (t == 0) {
        volatile int* dp = &g_done[b];
        while (*dp < PROD_BLOCKS) { __nanosleep(128); }
    }
    __syncthreads();
    __threadfence();

    // ---- hierarchical suffix sums: sfx[i] = #candidates with bin >= i ----
    const int PER = NB / TPB;   // 9
    int lo = t * PER;
    int ls = 0;
    #pragma unroll
    for (int i = 0; i < PER; i++) ls += g_hist[b][lo + i];
    int v = ls;
    #pragma unroll
    for (int off = 1; off < 32; off <<= 1) {
        int u = __shfl_down_sync(FULLM, v, off);
        if (lane + off < 32) v += u;
    }
    if (lane == 0) sm->wtot[warp] = v;
    __syncthreads();
    if (t < 32) {
        int x = sm->wtot[t];
        int vv = x;
        #pragma unroll
        for (int off = 1; off < 32; off <<= 1) {
            int u = __shfl_down_sync(FULLM, vv, off);
            if (t + off < 32) vv += u;
        }
        sm->wexc[t] = vv - x;
    }
    if (t == 0) sm->s_acc = 0;
    __syncthreads();
    int run = sm->wexc[warp] + (v - ls);
    for (int i = PER - 1; i >= 0; i--) {
        run += g_hist[b][lo + i];
        sm->sfx[lo + i] = run;
    }
    __syncthreads();

    int Ktot = min(g_cnt[b], CAPc);
    int b_hi = NB;

    while (sm->s_acc < DETS) {
        int top = (b_hi < NB) ? sm->sfx[b_hi] : 0;
        if (b_hi == 0 || sm->sfx[0] - top == 0) break;

        // smallest b_lo with sfx[b_lo] - top <= SEL_CAP
        int sl = 0, sh = b_hi;
        while (sl < sh) {
            int mid = (sl + sh) >> 1;
            if (sm->sfx[mid] - top <= SEL_CAP) sh = mid; else sl = mid + 1;
        }
        int wlo = sl;
        if (wlo >= b_hi) wlo = b_hi - 1;
        int whi = b_hi;
        b_hi = wlo;

        if (t == 0) sm->s_cnt = 0;
        __syncthreads();
        // ---- MLP-8 selection scan: batch 8 coalesced loads per iteration ----
        for (int i0 = 0; i0 < Ktot; i0 += TPB * 8) {
            unsigned long long kv[8];
            #pragma unroll
            for (int k = 0; k < 8; k++) {
                int i = i0 + k * TPB + t;
                kv[k] = (i < Ktot) ? g_keys[b][i] : 0ULL;
            }
            #pragma unroll
            for (int k = 0; k < 8; k++) {
                if (kv[k]) {    // real keys have nonzero score bits
                    int bin = (int)((unsigned)(kv[k] >> 32) >> 12) - BASE_BIN;
                    bin = max(0, min(bin, NB - 1));
                    if (bin >= wlo && bin < whi) {
                        int pos = atomicAdd(&sm->s_cnt, 1);
                        if (pos < SEL_CAP) sm->skey[pos] = kv[k];
                    }
                }
            }
        }
        __syncthreads();
        int nsel = min(sm->s_cnt, SEL_CAP);
        if (nsel == 0) continue;

        // pad to fixed P = SEL_CAP with 0-keys (sort to the tail)
        for (int i = nsel + t; i < SEL_CAP; i += TPB) sm->skey[i] = 0ULL;
        __syncthreads();

        // ---- register+shfl bitonic sort, descending, P=1024 ----
        {
            unsigned long long key = sm->skey[t];
            #pragma unroll
            for (int k2 = 2; k2 <= SEL_CAP; k2 <<= 1) {
                for (int j = k2 >> 1; j > 0; j >>= 1) {
                    unsigned long long partner;
                    if (j >= 32) {
                        __syncthreads();
                        sm->skey[t] = key;
                        __syncthreads();
                        partner = sm->skey[t ^ j];
                    } else {
                        partner = __shfl_xor_sync(FULLM, key, j);
                    }
                    bool desc    = ((t & k2) == 0);
                    bool lowerIx = ((t & j) == 0);
                    bool takeMax = (desc == lowerIx);
                    bool pG      = (partner > key);
                    if (takeMax == pG) key = partner;
                }
            }
            __syncthreads();
            sm->skey[t] = key;
            __syncthreads();
        }

        // ---- gather boxes + labels in sorted order ----
        for (int i = t; i < nsel; i += TPB) {
            unsigned m = 0xFFFFFFFFu - (unsigned)sm->skey[i];
            sm->sbox[i] = g_box[b][m];
            sm->slbl[i] = 1 + (int)(m % 90u);
        }
        __syncthreads();

        // ---- tiled mask-matrix NMS ----
        for (int j0 = 0; j0 < nsel; j0 += TILE) {
            int takeN = min(TILE, nsel - j0);
            if (t < 8) sm->supw[t] = 0;
            __syncthreads();
            int acc0 = sm->s_acc;

            // phase A: suppression by already-accepted boxes
            {
                int i = t & (TILE - 1);
                int q = t >> 8;                  // 0..3
                bool sup = false;
                if (i < takeN) {
                    float4 bi = sm->sbox[j0 + i];
                    int li = sm->slbl[j0 + i];
                    float off = (float)li * 801.0f;
                    for (int a = q; a < acc0; a += 4) {
                        if (sm->albl[a] == li && iou_sup(sm->abox[a], bi, off))
                            { sup = true; break; }
                    }
                }
                if (sup) atomicOr(&sm->supw[i >> 5], 1u << (i & 31));
            }

            // phase B: within-tile suppression mask (owner-exclusive words)
            for (int idx = t; idx < TILE * 8; idx += TPB) {
                int i = idx >> 3, w2 = idx & 7;
                unsigned bits = 0;
                if (i < takeN && (w2 * 32 + 31) > i) {
                    float4 bi = sm->sbox[j0 + i];
                    int li = sm->slbl[j0 + i];
                    float off = (float)li * 801.0f;
                    int jb = max(w2 * 32, i + 1);
                    int je = min(takeN, w2 * 32 + 32);
                    for (int j = jb; j < je; j++) {
                        if (sm->slbl[j0 + j] == li &&
                            iou_sup(bi, sm->sbox[j0 + j], off))
                            bits |= 1u << (j - w2 * 32);
                    }
                }
                sm->mask[i * 8 + w2] = bits;
            }
            __syncthreads();

            // phase C: warp 0 word-walk (greedy accept in sorted order)
            if (t < 32) {
                int acc = acc0;
                unsigned remv = (lane < 8) ? sm->supw[lane] : 0u;
                for (int basew = 0; basew < takeN && acc < DETS; basew += 32) {
                    int wi = basew >> 5;
                    unsigned word = __shfl_sync(FULLM, remv, wi);
                    unsigned lim = (takeN - basew >= 32) ? FULLM
                                   : ((1u << (takeN - basew)) - 1u);
                    unsigned alive = ~word & lim;
                    while (alive && acc < DETS) {
                        int pbit = __ffs(alive) - 1;
                        int i = basew + pbit;
                        unsigned mrow = (lane < 8) ? sm->mask[i * 8 + lane] : 0u;
                        remv |= mrow;
                        if (lane == 0) {
                            float4 bx = sm->sbox[j0 + i];
                            int lbl = sm->slbl[j0 + i];
                            sm->abox[acc] = bx;
                            sm->albl[acc] = lbl;
                            float sc = __uint_as_float((unsigned)(sm->skey[j0 + i] >> 32));
                            stf(out, b * (DETS * 4) + acc * 4 + 0, bx.x, out_size);
                            stf(out, b * (DETS * 4) + acc * 4 + 1, bx.y, out_size);
                            stf(out, b * (DETS * 4) + acc * 4 + 2, bx.z, out_size);
                            stf(out, b * (DETS * 4) + acc * 4 + 3, bx.w, out_size);
                            stf(out, Bn * DETS * 4 + b * DETS + acc, sc, out_size);
                            stf(out, Bn * DETS * 5 + b * DETS + acc, (float)lbl, out_size);
                            stf(out, Bn * DETS * 6 + b * DETS + acc, 1.0f, out_size);
                        }
                        acc++;
                        unsigned nw = __shfl_sync(FULLM, remv, wi);
                        alive &= ~nw;
                        alive &= ~(1u << pbit);
                    }
                }
                if (lane == 0) sm->s_acc = acc;
            }
            __syncthreads();
            if (sm->s_acc >= DETS) break;
        }
        __syncthreads();
    }

    // ---- zero-fill remaining detection slots ----
    __syncthreads();
    int accF = sm->s_acc;
    for (int a = accF + t; a < DETS; a += TPB) {
        stf(out, b * (DETS * 4) + a * 4 + 0, 0.f, out_size);
        stf(out, b * (DETS * 4) + a * 4 + 1, 0.f, out_size);
        stf(out, b * (DETS * 4) + a * 4 + 2, 0.f, out_size);
        stf(out, b * (DETS * 4) + a * 4 + 3, 0.f, out_size);
        stf(out, Bn * DETS * 4 + b * DETS + a, 0.f, out_size);
        stf(out, Bn * DETS * 5 + b * DETS + a, 0.f, out_size);
        stf(out, Bn * DETS * 6 + b * DETS + a, 0.f, out_size);
    }

    // ---- restore zeros for next graph replay ----
    for (int i = t; i < NB; i += TPB) g_hist[b][i] = 0;
    if (t == 0) { g_cnt[b] = 0; g_done[b] = 0; }
}

// ------------------------------------------------------------------
// launcher
// ------------------------------------------------------------------
extern "C" void kernel_launch(void* const* d_in, const int* in_sizes, int n_in,
                              void* d_out, int out_size) {
    const float* logits = nullptr;
    const float* reg    = nullptr;
    const float* props  = nullptr;
    for (int i = 0; i < n_in; i++) {
        if      (in_sizes[i] == Bn * Nn * Cn)     logits = (const float*)d_in[i];
        else if (in_sizes[i] == Bn * Nn * Cn * 4) reg    = (const float*)d_in[i];
        else if (in_sizes[i] == Bn * Nn * 4)      props  = (const float*)d_in[i];
    }
    if (!logits && n_in > 0) logits = (const float*)d_in[0];
    if (!reg    && n_in > 1) reg    = (const float*)d_in[1];
    if (!props  && n_in > 2) props  = (const float*)d_in[2];

    cudaFuncSetAttribute(k_fused, cudaFuncAttributeMaxDynamicSharedMemorySize,
                         (int)sizeof(SM));

    k_fused<<<33 * Bn, TPB, sizeof(SM)>>>(logits, reg, props,
                                          (float*)d_out, out_size);
}

// round 7
// speedup vs baseline: 1.1083x; 1.1083x over previous
#include <cuda_runtime.h>
#include <cstdint>

#define Bn    8
#define Nn    8192
#define Cn    91
#define Mx    (Nn*(Cn-1))     // 737280 flat candidate ids per image
#define CAPc  163840          // >= max kept candidates per image (19/proposal max)
#define NB    9216            // histogram bins over score float bits >> 12
#define BASE_BIN 251084       // bits(0.05f) >> 12
#define SEL_CAP 1024
#define TPB   1024
#define DETS  100
#define CLIPV 4.135166556742356f   // log(1000/16)
#define FULLM 0xffffffffu

// ------------------------------------------------------------------
// static device scratch (zero-initialized at load; k_nms restores the
// zeros it consumed -> graph-replay deterministic)
// ------------------------------------------------------------------
__device__ unsigned long long g_keys[Bn][CAPc];
__device__ float4             g_box [Bn][Mx];
__device__ int                g_cnt [Bn];
__device__ int                g_hist[Bn][NB];

__device__ __forceinline__ void stf(float* o, int i, float v, int n) {
    if (i < n) o[i] = v;
}

// reference-rounding IoU on offset coordinates; returns (iou > 0.5)
__device__ __forceinline__ bool iou_sup(float4 A, float4 Bx, float off) {
    float ax1 = A.x + off, ay1 = A.y + off, ax2 = A.z + off, ay2 = A.w + off;
    float bx1 = Bx.x + off, by1 = Bx.y + off, bx2 = Bx.z + off, by2 = Bx.w + off;
    float ltx = fmaxf(ax1, bx1), lty = fmaxf(ay1, by1);
    float rbx = fminf(ax2, bx2), rby = fminf(ay2, by2);
    float ww = fmaxf(rbx - ltx, 0.f), hh = fmaxf(rby - lty, 0.f);
    float inter = ww * hh;
    float a1 = (ax2 - ax1) * (ay2 - ay1);
    float a2 = (bx2 - bx1) * (by2 - by1);
    float iou = __fdiv_rn(inter, a1 + a2 - inter + 1e-9f);
    return iou > 0.5f;
}

// ------------------------------------------------------------------
// K1: softmax + prefilter + warp-compacted decode + write
// ------------------------------------------------------------------
__global__ __launch_bounds__(256) void k_cand(const float* __restrict__ logits,
                                              const float* __restrict__ reg,
                                              const float* __restrict__ props) {
    int g    = blockIdx.x * 8 + (threadIdx.x >> 5);   // proposal 0..65535
    int lane = threadIdx.x & 31;
    int b = g >> 13;
    int n = g & (Nn - 1);

    const float* L = logits + (size_t)g * Cn;
    float l0 = L[lane];
    float l1 = (lane + 32 < Cn) ? L[lane + 32] : -1e30f;
    float l2 = (lane + 64 < Cn) ? L[lane + 64] : -1e30f;

    float mx = fmaxf(l0, fmaxf(l1, l2));
    #pragma unroll
    for (int o = 16; o; o >>= 1) mx = fmaxf(mx, __shfl_xor_sync(FULLM, mx, o));

    float e0 = expf(l0 - mx);
    float e1 = (lane + 32 < Cn) ? expf(l1 - mx) : 0.0f;
    float e2 = (lane + 64 < Cn) ? expf(l2 - mx) : 0.0f;
    float s = e0 + e1 + e2;
    #pragma unroll
    for (int o = 16; o; o >>= 1) s += __shfl_xor_sync(FULLM, s, o);

    // conservative prefilter (margin >> 1ulp; exact test after compaction)
    float pre_t = 0.0497f * s;
    bool ok0 = (lane >= 1) && (e0 > pre_t);   // c = lane   (class 0 excluded)
    bool ok1 = (e1 > pre_t);                  // c = lane+32
    bool ok2 = (e2 > pre_t);                  // c = lane+64 (>=91 has e2=0)

    unsigned mA = __ballot_sync(FULLM, ok0);
    unsigned mB = __ballot_sync(FULLM, ok1);
    unsigned mC = __ballot_sync(FULLM, ok2);
    int c0  = __popc(mA);
    int c01 = c0 + __popc(mB);
    int tot = c01 + __popc(mC);
    if (tot == 0) return;                     // warp-uniform

    // compact candidates into lanes [0, tot)
    int src = 0, k = 0;
    if (lane < c0)       { k = 0; src = __fns(mA, 0, lane + 1); }
    else if (lane < c01) { k = 1; src = __fns(mB, 0, lane - c0 + 1); }
    else if (lane < tot) { k = 2; src = __fns(mC, 0, lane - c01 + 1); }
    src &= 31;
    float eA = __shfl_sync(FULLM, e0, src);
    float eB = __shfl_sync(FULLM, e1, src);
    float eC = __shfl_sync(FULLM, e2, src);
    float e  = (k == 2) ? eC : ((k == 1) ? eB : eA);
    int   c  = src + (k << 5);

    bool ok = (lane < tot);
    float sc = __fdiv_rn(e, s);               // exact softmax value
    ok = ok && (sc > 0.05f);

    // proposal geometry (broadcast)
    float4 p = reinterpret_cast<const float4*>(props)[g];
    float w  = p.z - p.x;
    float h  = p.w - p.y;
    float cx = p.x + 0.5f * w;
    float cy = p.y + 0.5f * h;

    float4 bx = make_float4(0.f, 0.f, 0.f, 0.f);
    if (ok) {
        const float4* Q = reinterpret_cast<const float4*>(reg + (size_t)g * (Cn * 4));
        float4 q = Q[c];
        float dx = __fdiv_rn(q.x, 10.0f);
        float dy = __fdiv_rn(q.y, 10.0f);
        float dw = fminf(__fdiv_rn(q.z, 5.0f), CLIPV);
        float dh = fminf(__fdiv_rn(q.w, 5.0f), CLIPV);
        float pcx = dx * w + cx;
        float pcy = dy * h + cy;
        float pw  = expf(dw) * w;
        float ph  = expf(dh) * h;
        float x1 = fminf(fmaxf(pcx - 0.5f * pw, 0.f), 800.f);
        float y1 = fminf(fmaxf(pcy - 0.5f * ph, 0.f), 800.f);
        float x2 = fminf(fmaxf(pcx + 0.5f * pw, 0.f), 800.f);
        float y2 = fminf(fmaxf(pcy + 0.5f * ph, 0.f), 800.f);
        ok = ((x2 - x1) >= 1.0f) && ((y2 - y1) >= 1.0f);
        bx = make_float4(x1, y1, x2, y2);
    }

    unsigned fm = __ballot_sync(FULLM, ok);
    int cnt = __popc(fm);
    if (cnt) {
        int base = 0;
        if (lane == 0) base = atomicAdd(&g_cnt[b], cnt);
        base = __shfl_sync(FULLM, base, 0);
        if (ok) {
            int pos = base + __popc(fm & ((1u << lane) - 1u));
            if (pos < CAPc) {
                unsigned m = (unsigned)(n * 90 + (c - 1));
                unsigned sb = __float_as_uint(sc);
                g_keys[b][pos] = ((unsigned long long)sb << 32) | (0xFFFFFFFFu - m);
                g_box[b][m]    = bx;
                int bin = (int)(sb >> 12) - BASE_BIN;
                bin = max(0, min(bin, NB - 1));
                atomicAdd(&g_hist[b][bin], 1);
            }
        }
    }
}

// ------------------------------------------------------------------
// K2 shared memory (separate kernel -> generous budget, ~130KB)
// ------------------------------------------------------------------
struct SM {
    float4 sbox[SEL_CAP];               // window boxes (sorted order)
    float4 cls_acc[32][DETS];           // per-warp class accepted scratch
    float4 abox[DETS];                  // global accepted boxes
    unsigned long long skey[SEL_CAP];
    int    slbl[SEL_CAP];
    int    sfx[NB];
    int    cls_rank[SEL_CAP];
    int    cls_list[SEL_CAP];
    int    sflag[SEL_CAP];
    int    cls_cnt[128];
    int    cls_off[96];
    int    albl[DETS];
    int    wtot[32], wexc[32], wsum[32];
    int    s_cnt, s_acc, s_surv;
};

__global__ __launch_bounds__(TPB) void k_nms(float* __restrict__ out, int out_size) {
    extern __shared__ __align__(16) char smraw[];
    SM* sm = reinterpret_cast<SM*>(smraw);
    int b = blockIdx.x;
    int t = threadIdx.x;
    int lane = t & 31;
    int warp = t >> 5;

    // ---- hierarchical suffix sums: sfx[i] = #candidates with bin >= i ----
    const int PER = NB / TPB;   // 9
    int lo = t * PER;
    int ls = 0;
    #pragma unroll
    for (int i = 0; i < PER; i++) ls += g_hist[b][lo + i];
    int v = ls;
    #pragma unroll
    for (int off = 1; off < 32; off <<= 1) {
        int u = __shfl_down_sync(FULLM, v, off);
        if (lane + off < 32) v += u;
    }
    if (lane == 0) sm->wtot[warp] = v;
    __syncthreads();
    if (t < 32) {
        int x = sm->wtot[t];
        int vv = x;
        #pragma unroll
        for (int off = 1; off < 32; off <<= 1) {
            int u = __shfl_down_sync(FULLM, vv, off);
            if (t + off < 32) vv += u;
        }
        sm->wexc[t] = vv - x;
    }
    if (t == 0) sm->s_acc = 0;
    __syncthreads();
    int run = sm->wexc[warp] + (v - ls);
    for (int i = PER - 1; i >= 0; i--) {
        run += g_hist[b][lo + i];
        sm->sfx[lo + i] = run;
    }
    __syncthreads();

    int Ktot = min(g_cnt[b], CAPc);
    int b_hi = NB;

    while (sm->s_acc < DETS) {
        int top = (b_hi < NB) ? sm->sfx[b_hi] : 0;
        if (b_hi == 0 || sm->sfx[0] - top == 0) break;

        // smallest b_lo with sfx[b_lo] - top <= SEL_CAP
        int sl = 0, sh = b_hi;
        while (sl < sh) {
            int mid = (sl + sh) >> 1;
            if (sm->sfx[mid] - top <= SEL_CAP) sh = mid; else sl = mid + 1;
        }
        int wlo = sl;
        if (wlo >= b_hi) wlo = b_hi - 1;
        int whi = b_hi;
        b_hi = wlo;

        if (t == 0) sm->s_cnt = 0;
        __syncthreads();
        // ---- MLP-8 selection scan ----
        for (int i0 = 0; i0 < Ktot; i0 += TPB * 8) {
            unsigned long long kv[8];
            #pragma unroll
            for (int k = 0; k < 8; k++) {
                int i = i0 + k * TPB + t;
                kv[k] = (i < Ktot) ? g_keys[b][i] : 0ULL;
            }
            #pragma unroll
            for (int k = 0; k < 8; k++) {
                if (kv[k]) {
                    int bin = (int)((unsigned)(kv[k] >> 32) >> 12) - BASE_BIN;
                    bin = max(0, min(bin, NB - 1));
                    if (bin >= wlo && bin < whi) {
                        int pos = atomicAdd(&sm->s_cnt, 1);
                        if (pos < SEL_CAP) sm->skey[pos] = kv[k];
                    }
                }
            }
        }
        __syncthreads();
        int nsel = min(sm->s_cnt, SEL_CAP);
        if (nsel == 0) continue;

        for (int i = nsel + t; i < SEL_CAP; i += TPB) sm->skey[i] = 0ULL;
        __syncthreads();

        // ---- register+shfl bitonic sort, descending, P=1024 ----
        {
            unsigned long long key = sm->skey[t];
            #pragma unroll
            for (int k2 = 2; k2 <= SEL_CAP; k2 <<= 1) {
                for (int j = k2 >> 1; j > 0; j >>= 1) {
                    unsigned long long partner;
                    if (j >= 32) {
                        __syncthreads();
                        sm->skey[t] = key;
                        __syncthreads();
                        partner = sm->skey[t ^ j];
                    } else {
                        partner = __shfl_xor_sync(FULLM, key, j);
                    }
                    bool desc    = ((t & k2) == 0);
                    bool lowerIx = ((t & j) == 0);
                    bool takeMax = (desc == lowerIx);
                    bool pG      = (partner > key);
                    if (takeMax == pG) key = partner;
                }
            }
            __syncthreads();
            sm->skey[t] = key;
            __syncthreads();
        }

        // ---- gather boxes + labels; reset flags/counters ----
        if (t < nsel) {
            unsigned m = 0xFFFFFFFFu - (unsigned)sm->skey[t];
            sm->sbox[t] = g_box[b][m];
            sm->slbl[t] = 1 + (int)(m % 90u);
        }
        sm->sflag[t] = 0;
        if (t < 128) sm->cls_cnt[t] = 0;
        __syncthreads();

        // ---- stable per-class ranks (single warp, 32 chunks) ----
        if (t < 32) {
            for (int k = 0; k < 32; k++) {
                int i = k * 32 + lane;
                int lbl = (i < nsel) ? sm->slbl[i] : (96 + lane);
                unsigned peers = __match_any_sync(FULLM, lbl);
                int leader = __ffs(peers) - 1;
                int rank = __popc(peers & ((1u << lane) - 1u));
                int base = 0;
                if (lane == leader) {
                    base = sm->cls_cnt[lbl];
                    sm->cls_cnt[lbl] = base + __popc(peers);
                }
                base = __shfl_sync(FULLM, base, leader);
                if (i < nsel) sm->cls_rank[i] = base + rank;
            }
        }
        __syncthreads();

        // ---- exclusive offsets over classes 0..95 ----
        if (t < 32) {
            int c0i = t * 3;
            int s0 = sm->cls_cnt[c0i], s1 = sm->cls_cnt[c0i + 1], s2 = sm->cls_cnt[c0i + 2];
            int tt = s0 + s1 + s2;
            int rn = tt;
            #pragma unroll
            for (int off = 1; off < 32; off <<= 1) {
                int u = __shfl_up_sync(FULLM, rn, off);
                if (lane >= off) rn += u;
            }
            int ex = rn - tt;
            sm->cls_off[c0i] = ex;
            sm->cls_off[c0i + 1] = ex + s0;
            sm->cls_off[c0i + 2] = ex + s0 + s1;
        }
        __syncthreads();

        // ---- scatter per-class lists (stable: score order within class) ----
        if (t < nsel) sm->cls_list[sm->cls_off[sm->slbl[t]] + sm->cls_rank[t]] = t;
        int acc0 = sm->s_acc;
        int quota = DETS - acc0;
        __syncthreads();

        // ---- per-class greedy NMS: warp w handles classes w+1, w+33, w+65 ----
        #pragma unroll
        for (int jc = 0; jc < 3; jc++) {
            int c = warp + 1 + 32 * jc;
            if (c > 90) continue;
            int cnt = sm->cls_cnt[c];
            if (cnt == 0) continue;
            int off = sm->cls_off[c];
            float offv = (float)c * 801.0f;

            // load prior accepted boxes of this class
            int nacc = 0;
            for (int a0 = 0; a0 < acc0; a0 += 32) {
                int a = a0 + lane;
                bool mth = (a < acc0) && (sm->albl[a] == c);
                unsigned mm = __ballot_sync(FULLM, mth);
                if (mth) sm->cls_acc[warp][nacc + __popc(mm & ((1u << lane) - 1u))] = sm->abox[a];
                nacc += __popc(mm);
            }

            int newacc = 0;
            for (int j = 0; j < cnt; j++) {
                int i = sm->cls_list[off + j];
                float4 bx = sm->sbox[i];
                bool sup = false;
                for (int a = lane; a < nacc; a += 32)
                    sup |= iou_sup(sm->cls_acc[warp][a], bx, offv);
                if (!__any_sync(FULLM, sup)) {
                    if (lane == 0) {
                        sm->sflag[i] = 1;
                        sm->cls_acc[warp][nacc] = bx;
                    }
                    nacc++;
                    newacc++;
                    if (newacc >= quota) break;   // deeper survivors can't be output
                }
            }
        }
        __syncthreads();

        // ---- prefix over survivor flags; output first quota in order ----
        {
            int f = sm->sflag[t];
            int scn = f;
            #pragma unroll
            for (int off = 1; off < 32; off <<= 1) {
                int u = __shfl_up_sync(FULLM, scn, off);
                if (lane >= off) scn += u;
            }
            if (lane == 31) sm->wsum[warp] = scn;
            __syncthreads();
            if (t < 32) {
                int x = sm->wsum[t];
                int s2 = x;
                #pragma unroll
                for (int off = 1; off < 32; off <<= 1) {
                    int u = __shfl_up_sync(FULLM, s2, off);
                    if (t >= off) s2 += u;
                }
                sm->wsum[t] = s2 - x;   // exclusive warp base
            }
            __syncthreads();
            int incl = scn + sm->wsum[warp];
            int r = incl - f;           // exclusive rank
            if (f && (acc0 + r) < DETS) {
                int slot = acc0 + r;
                float4 bx = sm->sbox[t];
                int lbl = sm->slbl[t];
                sm->abox[slot] = bx;
                sm->albl[slot] = lbl;
                float sc = __uint_as_float((unsigned)(sm->skey[t] >> 32));
                stf(out, b * (DETS * 4) + slot * 4 + 0, bx.x, out_size);
                stf(out, b * (DETS * 4) + slot * 4 + 1, bx.y, out_size);
                stf(out, b * (DETS * 4) + slot * 4 + 2, bx.z, out_size);
                stf(out, b * (DETS * 4) + slot * 4 + 3, bx.w, out_size);
                stf(out, Bn * DETS * 4 + b * DETS + slot, sc, out_size);
                stf(out, Bn * DETS * 5 + b * DETS + slot, (float)lbl, out_size);
                stf(out, Bn * DETS * 6 + b * DETS + slot, 1.0f, out_size);
            }
            if (t == TPB - 1) sm->s_surv = incl;
            __syncthreads();
            if (t == 0) sm->s_acc = min(acc0 + sm->s_surv, DETS);
            __syncthreads();
        }
    }

    // ---- zero-fill remaining detection slots ----
    __syncthreads();
    int accF = sm->s_acc;
    for (int a = accF + t; a < DETS; a += TPB) {
        stf(out, b * (DETS * 4) + a * 4 + 0, 0.f, out_size);
        stf(out, b * (DETS * 4) + a * 4 + 1, 0.f, out_size);
        stf(out, b * (DETS * 4) + a * 4 + 2, 0.f, out_size);
        stf(out, b * (DETS * 4) + a * 4 + 3, 0.f, out_size);
        stf(out, Bn * DETS * 4 + b * DETS + a, 0.f, out_size);
        stf(out, Bn * DETS * 5 + b * DETS + a, 0.f, out_size);
        stf(out, Bn * DETS * 6 + b * DETS + a, 0.f, out_size);
    }

    // ---- restore zeros for next graph replay ----
    for (int i = t; i < NB; i += TPB) g_hist[b][i] = 0;
    if (t == 0) g_cnt[b] = 0;
}

// ------------------------------------------------------------------
// launcher
// ------------------------------------------------------------------
extern "C" void kernel_launch(void* const* d_in, const int* in_sizes, int n_in,
                              void* d_out, int out_size) {
    const float* logits = nullptr;
    const float* reg    = nullptr;
    const float* props  = nullptr;
    for (int i = 0; i < n_in; i++) {
        if      (in_sizes[i] == Bn * Nn * Cn)     logits = (const float*)d_in[i];
        else if (in_sizes[i] == Bn * Nn * Cn * 4) reg    = (const float*)d_in[i];
        else if (in_sizes[i] == Bn * Nn * 4)      props  = (const float*)d_in[i];
    }
    if (!logits && n_in > 0) logits = (const float*)d_in[0];
    if (!reg    && n_in > 1) reg    = (const float*)d_in[1];
    if (!props  && n_in > 2) props  = (const float*)d_in[2];

    cudaFuncSetAttribute(k_nms, cudaFuncAttributeMaxDynamicSharedMemorySize,
                         (int)sizeof(SM));

    k_cand<<<(Bn * Nn) / 8, 256>>>(logits, reg, props);
    k_nms<<<Bn, TPB, sizeof(SM)>>>((float*)d_out, out_size);
}